// round 1
// baseline (speedup 1.0000x reference)
#include <cuda_runtime.h>

#define GRIDSZ 64
#define NVOX (GRIDSZ*GRIDSZ*GRIDSZ)
#define NFEAT 16
#define NODES 128
#define DIN 52
#define PTS 64                 // points per tile
#define THREADS 256
#define PI_F 3.14159265358979323846f

// ---- device scratch (no runtime allocation allowed) ----
__device__ float g_tg[NVOX * NFEAT];        // channels-last grid [z][y][x][c]
__device__ float g_W0T[DIN * NODES];        // W0 transposed: [k][j]
__device__ float g_WhT[3 * NODES * NODES];  // Wh transposed: [l][k][j]

// ---------------- prep kernels ----------------
__global__ void prep_grid_k(const float* __restrict__ grid) {
    int v = blockIdx.x * blockDim.x + threadIdx.x;
    if (v >= NVOX) return;
    float4 r0, r1, r2, r3;
    r0.x = grid[0*NVOX+v];  r0.y = grid[1*NVOX+v];  r0.z = grid[2*NVOX+v];  r0.w = grid[3*NVOX+v];
    r1.x = grid[4*NVOX+v];  r1.y = grid[5*NVOX+v];  r1.z = grid[6*NVOX+v];  r1.w = grid[7*NVOX+v];
    r2.x = grid[8*NVOX+v];  r2.y = grid[9*NVOX+v];  r2.z = grid[10*NVOX+v]; r2.w = grid[11*NVOX+v];
    r3.x = grid[12*NVOX+v]; r3.y = grid[13*NVOX+v]; r3.z = grid[14*NVOX+v]; r3.w = grid[15*NVOX+v];
    float4* dst = reinterpret_cast<float4*>(&g_tg[(size_t)v * NFEAT]);
    dst[0] = r0; dst[1] = r1; dst[2] = r2; dst[3] = r3;
}

__global__ void prep_w_k(const float* __restrict__ W0, const float* __restrict__ Wh) {
    int t = blockIdx.x * blockDim.x + threadIdx.x;
    int nt = gridDim.x * blockDim.x;
    for (int i = t; i < DIN * NODES; i += nt) {
        int k = i / NODES, j = i - k * NODES;
        g_W0T[i] = W0[j * DIN + k];
    }
    for (int i = t; i < 3 * NODES * NODES; i += nt) {
        int l = i >> 14;              // / 16384
        int r = i & 16383;
        int k = r >> 7, j = r & 127;
        g_WhT[i] = Wh[l * 16384 + j * NODES + k];
    }
}

// ---------------- packed fp32x2 FMA ----------------
__device__ __forceinline__ float2 ffma2(float2 a, float2 b, float2 c) {
    unsigned long long ua = *reinterpret_cast<unsigned long long*>(&a);
    unsigned long long ub = *reinterpret_cast<unsigned long long*>(&b);
    unsigned long long uc = *reinterpret_cast<unsigned long long*>(&c);
    unsigned long long ud;
    asm("fma.rn.f32x2 %0, %1, %2, %3;" : "=l"(ud) : "l"(ua), "l"(ub), "l"(uc));
    return *reinterpret_cast<float2*>(&ud);
}

// One dense layer: out[j][p] = snake( sum_k W[k][j] * Acts[k][p] + b[j] )
// Acts layout: [K rows][64 points], k-major, row pitch 64 floats.
// W layout: [K][128] (k-major). Thread tile: 4 points x 8 neurons.
__device__ __forceinline__ void do_layer(const float* __restrict__ Wk,
                                         const float* __restrict__ bias,
                                         float* sActs, int K, int tx, int ty) {
    const int p0 = tx * 4;
    const int j0 = ty * 8;
    float2 acc[4][4];
    {
        float4 bA = *reinterpret_cast<const float4*>(&bias[j0]);
        float4 bB = *reinterpret_cast<const float4*>(&bias[j0 + 4]);
#pragma unroll
        for (int p = 0; p < 4; p++) {
            acc[p][0] = make_float2(bA.x, bA.y);
            acc[p][1] = make_float2(bA.z, bA.w);
            acc[p][2] = make_float2(bB.x, bB.y);
            acc[p][3] = make_float2(bB.z, bB.w);
        }
    }
#pragma unroll 4
    for (int k = 0; k < K; k++) {
        float4 a  = *reinterpret_cast<const float4*>(&sActs[k * PTS + p0]);
        float4 wA = *reinterpret_cast<const float4*>(&Wk[k * NODES + j0]);
        float4 wB = *reinterpret_cast<const float4*>(&Wk[k * NODES + j0 + 4]);
        float2 w[4];
        w[0] = make_float2(wA.x, wA.y); w[1] = make_float2(wA.z, wA.w);
        w[2] = make_float2(wB.x, wB.y); w[3] = make_float2(wB.z, wB.w);
        float av[4] = {a.x, a.y, a.z, a.w};
#pragma unroll
        for (int p = 0; p < 4; p++) {
            float2 ap = make_float2(av[p], av[p]);
#pragma unroll
            for (int jj = 0; jj < 4; jj++) acc[p][jj] = ffma2(ap, w[jj], acc[p][jj]);
        }
    }
    __syncthreads();   // all reads of sActs done; safe to overwrite
#pragma unroll
    for (int p = 0; p < 4; p++) {
#pragma unroll
        for (int jj = 0; jj < 4; jj++) {
            float zx = acc[p][jj].x, zy = acc[p][jj].y;
            float sx = __sinf(zx), sy = __sinf(zy);
            sActs[(j0 + jj * 2)     * PTS + p0 + p] = fmaf(0.5f, zx, sx * sx);
            sActs[(j0 + jj * 2 + 1) * PTS + p0 + p] = fmaf(0.5f, zy, sy * sy);
        }
    }
    __syncthreads();
}

// ---------------- main fused kernel ----------------
__global__ void __launch_bounds__(THREADS, 1)
fvsrn_main(const float* __restrict__ x, const float* __restrict__ b0,
           const float* __restrict__ bh, const float* __restrict__ Wout,
           const float* __restrict__ bout, float* __restrict__ out,
           int Np, int ntiles) {
    extern __shared__ float smem[];
    float* sWh   = smem;                 // 3*128*128 = 49152 floats
    float* sActs = sWh + 3 * NODES * NODES;   // 128*64 = 8192 floats
    float* sB    = sActs + NODES * PTS;       // 512 floats: b0, bh[0..2]
    float* sWo   = sB + 512;                  // 128 floats

    const int tid = threadIdx.x;
    for (int i = tid; i < 3 * NODES * NODES; i += THREADS) sWh[i] = g_WhT[i];
    for (int i = tid; i < 512; i += THREADS) sB[i] = (i < NODES) ? b0[i] : bh[i - NODES];
    if (tid < NODES) sWo[tid] = Wout[tid];
    const float bo = bout[0];
    __syncthreads();

    const int tx = tid & 15, ty = tid >> 4;   // GEMM thread tile coords
    const int pl = tid >> 2, sub = tid & 3;   // stage-1/out coords: 4 threads per point
    const float4* tg4 = reinterpret_cast<const float4*>(g_tg);

    for (int tile = blockIdx.x; tile < ntiles; tile += gridDim.x) {
        const int pg = tile * PTS + pl;
        float xv0 = 0.f, xv1 = 0.f, xv2 = 0.f;
        if (pg < Np) { xv0 = x[pg*3+0]; xv1 = x[pg*3+1]; xv2 = x[pg*3+2]; }

        // ---- positional encoding: rows 0..35, this thread writes 9 of them
#pragma unroll
        for (int i0 = 0; i0 < 9; i0++) {
            int i = sub * 9 + i0;
            int l = i / 6;
            int r = i - l * 6;
            int d = (r >= 3) ? (r - 3) : r;
            float v = (d == 0) ? xv0 : ((d == 1) ? xv1 : xv2);
            float arg = v * (PI_F * (float)(1 << l));
            float s, c;
            __sincosf(arg, &s, &c);
            sActs[i * PTS + pl] = (r < 3) ? s : c;
        }

        // ---- trilinear grid sample: rows 36..51, this thread does 4 channels
        {
            float fx = (xv0 + 1.f) * 31.5f;
            float fy = (xv1 + 1.f) * 31.5f;
            float fz = (xv2 + 1.f) * 31.5f;
            int ix0 = min(max((int)floorf(fx), 0), 63); int ix1 = min(ix0 + 1, 63);
            int iy0 = min(max((int)floorf(fy), 0), 63); int iy1 = min(iy0 + 1, 63);
            int iz0 = min(max((int)floorf(fz), 0), 63); int iz1 = min(iz0 + 1, 63);
            float wx1 = fx - (float)ix0, wx0 = 1.f - wx1;
            float wy1 = fy - (float)iy0, wy0 = 1.f - wy1;
            float wz1 = fz - (float)iz0, wz0 = 1.f - wz1;
            int   xs[2] = {ix0, ix1}, ys[2] = {iy0, iy1}, zs[2] = {iz0, iz1};
            float wxs[2] = {wx0, wx1}, wys[2] = {wy0, wy1}, wzs[2] = {wz0, wz1};
            float4 f4 = make_float4(0.f, 0.f, 0.f, 0.f);
#pragma unroll
            for (int iz = 0; iz < 2; iz++)
#pragma unroll
                for (int iy = 0; iy < 2; iy++)
#pragma unroll
                    for (int ix = 0; ix < 2; ix++) {
                        float w = wzs[iz] * wys[iy] * wxs[ix];
                        int vox = (zs[iz] * 64 + ys[iy]) * 64 + xs[ix];
                        float4 t = tg4[vox * 4 + sub];
                        f4.x = fmaf(w, t.x, f4.x);
                        f4.y = fmaf(w, t.y, f4.y);
                        f4.z = fmaf(w, t.z, f4.z);
                        f4.w = fmaf(w, t.w, f4.w);
                    }
            int fr = 36 + sub * 4;
            sActs[(fr + 0) * PTS + pl] = f4.x;
            sActs[(fr + 1) * PTS + pl] = f4.y;
            sActs[(fr + 2) * PTS + pl] = f4.z;
            sActs[(fr + 3) * PTS + pl] = f4.w;
        }
        __syncthreads();

        // ---- MLP: 52->128, then 3x 128->128 (all snake-activated)
        do_layer(g_W0T,              sB,       sActs, DIN,   tx, ty);
        do_layer(sWh,                sB + 128, sActs, NODES, tx, ty);
        do_layer(sWh + NODES*NODES,  sB + 256, sActs, NODES, tx, ty);
        do_layer(sWh + 2*NODES*NODES,sB + 384, sActs, NODES, tx, ty);

        // ---- output layer: 128 -> 1 (4 threads per point, shuffle reduce)
        {
            float r = 0.f;
            int kbase = sub * 32;
#pragma unroll 8
            for (int k = 0; k < 32; k++)
                r = fmaf(sWo[kbase + k], sActs[(kbase + k) * PTS + pl], r);
            r += __shfl_xor_sync(0xffffffffu, r, 1);
            r += __shfl_xor_sync(0xffffffffu, r, 2);
            if (sub == 0 && pg < Np) out[pg] = r + bo;
        }
        __syncthreads();   // protect sActs reads vs next tile's stage-1 writes
    }
}

// ---------------- launch ----------------
extern "C" void kernel_launch(void* const* d_in, const int* in_sizes, int n_in,
                              void* d_out, int out_size) {
    const float* x    = (const float*)d_in[0];
    const float* grid = (const float*)d_in[1];
    const float* W0   = (const float*)d_in[2];
    const float* b0   = (const float*)d_in[3];
    const float* Wh   = (const float*)d_in[4];
    const float* bh   = (const float*)d_in[5];
    const float* Wout = (const float*)d_in[6];
    const float* bout = (const float*)d_in[7];
    float* out = (float*)d_out;

    int Np = in_sizes[0] / 3;
    int ntiles = (Np + PTS - 1) / PTS;

    prep_grid_k<<<(NVOX + 255) / 256, 256>>>(grid);
    prep_w_k<<<64, 256>>>(W0, Wh);

    const int smem_bytes = (3 * NODES * NODES + NODES * PTS + 512 + 128) * (int)sizeof(float);
    cudaFuncSetAttribute(fvsrn_main, cudaFuncAttributeMaxDynamicSharedMemorySize, smem_bytes);
    fvsrn_main<<<148, THREADS, smem_bytes>>>(x, b0, bh, Wout, bout, out, Np, ntiles);
}

// round 2
// speedup vs baseline: 1.0020x; 1.0020x over previous
#include <cuda_runtime.h>

#define GRIDSZ 64
#define NVOX (GRIDSZ*GRIDSZ*GRIDSZ)
#define NFEAT 16
#define NODES 128
#define DIN 52
#define PTS 64                 // points per tile
#define THREADS 256
#define PI_F 3.14159265358979323846f

// ---- device scratch (no runtime allocation allowed) ----
__device__ float g_tg[NVOX * NFEAT];        // channels-last grid [z][y][x][c]
__device__ float g_W0T[DIN * NODES];        // W0 transposed: [k][j]
__device__ float g_WhT[3 * NODES * NODES];  // Wh transposed: [l][k][j]

// ---------------- prep kernels ----------------
__global__ void prep_grid_k(const float* __restrict__ grid) {
    int v = blockIdx.x * blockDim.x + threadIdx.x;
    if (v >= NVOX) return;
    float4 r0, r1, r2, r3;
    r0.x = grid[0*NVOX+v];  r0.y = grid[1*NVOX+v];  r0.z = grid[2*NVOX+v];  r0.w = grid[3*NVOX+v];
    r1.x = grid[4*NVOX+v];  r1.y = grid[5*NVOX+v];  r1.z = grid[6*NVOX+v];  r1.w = grid[7*NVOX+v];
    r2.x = grid[8*NVOX+v];  r2.y = grid[9*NVOX+v];  r2.z = grid[10*NVOX+v]; r2.w = grid[11*NVOX+v];
    r3.x = grid[12*NVOX+v]; r3.y = grid[13*NVOX+v]; r3.z = grid[14*NVOX+v]; r3.w = grid[15*NVOX+v];
    float4* dst = reinterpret_cast<float4*>(&g_tg[(size_t)v * NFEAT]);
    dst[0] = r0; dst[1] = r1; dst[2] = r2; dst[3] = r3;
}

__global__ void prep_w_k(const float* __restrict__ W0, const float* __restrict__ Wh) {
    int t = blockIdx.x * blockDim.x + threadIdx.x;
    int nt = gridDim.x * blockDim.x;
    for (int i = t; i < DIN * NODES; i += nt) {
        int k = i / NODES, j = i - k * NODES;
        g_W0T[i] = W0[j * DIN + k];
    }
    for (int i = t; i < 3 * NODES * NODES; i += nt) {
        int l = i >> 14;              // / 16384
        int r = i & 16383;
        int k = r >> 7, j = r & 127;
        g_WhT[i] = Wh[l * 16384 + j * NODES + k];
    }
}

// ---------------- packed fp32x2 FMA ----------------
__device__ __forceinline__ float2 ffma2(float2 a, float2 b, float2 c) {
    unsigned long long ua = *reinterpret_cast<unsigned long long*>(&a);
    unsigned long long ub = *reinterpret_cast<unsigned long long*>(&b);
    unsigned long long uc = *reinterpret_cast<unsigned long long*>(&c);
    unsigned long long ud;
    asm("fma.rn.f32x2 %0, %1, %2, %3;" : "=l"(ud) : "l"(ua), "l"(ub), "l"(uc));
    return *reinterpret_cast<float2*>(&ud);
}

// One dense layer: out[j][p] = snake( sum_k W[k][j] * Acts[k][p] + b[j] )
// Acts layout: [K rows][64 points], k-major, row pitch 64 floats.
// W layout: [K][128] (k-major). Thread tile: 4 points x 8 neurons.
__device__ __forceinline__ void do_layer(const float* __restrict__ Wk,
                                         const float* __restrict__ bias,
                                         float* sActs, int K, int tx, int ty) {
    const int p0 = tx * 4;
    const int j0 = ty * 8;
    float2 acc[4][4];
    {
        float4 bA = *reinterpret_cast<const float4*>(&bias[j0]);
        float4 bB = *reinterpret_cast<const float4*>(&bias[j0 + 4]);
#pragma unroll
        for (int p = 0; p < 4; p++) {
            acc[p][0] = make_float2(bA.x, bA.y);
            acc[p][1] = make_float2(bA.z, bA.w);
            acc[p][2] = make_float2(bB.x, bB.y);
            acc[p][3] = make_float2(bB.z, bB.w);
        }
    }
#pragma unroll 4
    for (int k = 0; k < K; k++) {
        float4 a  = *reinterpret_cast<const float4*>(&sActs[k * PTS + p0]);
        float4 wA = *reinterpret_cast<const float4*>(&Wk[k * NODES + j0]);
        float4 wB = *reinterpret_cast<const float4*>(&Wk[k * NODES + j0 + 4]);
        float2 w[4];
        w[0] = make_float2(wA.x, wA.y); w[1] = make_float2(wA.z, wA.w);
        w[2] = make_float2(wB.x, wB.y); w[3] = make_float2(wB.z, wB.w);
        float av[4] = {a.x, a.y, a.z, a.w};
#pragma unroll
        for (int p = 0; p < 4; p++) {
            float2 ap = make_float2(av[p], av[p]);
#pragma unroll
            for (int jj = 0; jj < 4; jj++) acc[p][jj] = ffma2(ap, w[jj], acc[p][jj]);
        }
    }
    __syncthreads();   // all reads of sActs done; safe to overwrite
#pragma unroll
    for (int p = 0; p < 4; p++) {
#pragma unroll
        for (int jj = 0; jj < 4; jj++) {
            float zx = acc[p][jj].x, zy = acc[p][jj].y;
            float sx = __sinf(zx), sy = __sinf(zy);
            sActs[(j0 + jj * 2)     * PTS + p0 + p] = fmaf(0.5f, zx, sx * sx);
            sActs[(j0 + jj * 2 + 1) * PTS + p0 + p] = fmaf(0.5f, zy, sy * sy);
        }
    }
    __syncthreads();
}

// ---------------- main fused kernel ----------------
__global__ void __launch_bounds__(THREADS, 1)
fvsrn_main(const float* __restrict__ x, const float* __restrict__ b0,
           const float* __restrict__ bh, const float* __restrict__ Wout,
           const float* __restrict__ bout, float* __restrict__ out,
           int Np, int ntiles) {
    extern __shared__ float smem[];
    float* sWh   = smem;                 // 3*128*128 = 49152 floats
    float* sActs = sWh + 3 * NODES * NODES;   // 128*64 = 8192 floats
    float* sB    = sActs + NODES * PTS;       // 512 floats: b0, bh[0..2]
    float* sWo   = sB + 512;                  // 128 floats

    const int tid = threadIdx.x;
    for (int i = tid; i < 3 * NODES * NODES; i += THREADS) sWh[i] = g_WhT[i];
    for (int i = tid; i < 512; i += THREADS) sB[i] = (i < NODES) ? b0[i] : bh[i - NODES];
    if (tid < NODES) sWo[tid] = Wout[tid];
    const float bo = bout[0];
    __syncthreads();

    const int tx = tid & 15, ty = tid >> 4;   // GEMM thread tile coords
    const int pl = tid >> 2, sub = tid & 3;   // stage-1/out coords: 4 threads per point
    const float4* tg4 = reinterpret_cast<const float4*>(g_tg);

    for (int tile = blockIdx.x; tile < ntiles; tile += gridDim.x) {
        const int pg = tile * PTS + pl;
        float xv0 = 0.f, xv1 = 0.f, xv2 = 0.f;
        if (pg < Np) { xv0 = x[pg*3+0]; xv1 = x[pg*3+1]; xv2 = x[pg*3+2]; }

        // ---- positional encoding: rows 0..35, this thread writes 9 of them
#pragma unroll
        for (int i0 = 0; i0 < 9; i0++) {
            int i = sub * 9 + i0;
            int l = i / 6;
            int r = i - l * 6;
            int d = (r >= 3) ? (r - 3) : r;
            float v = (d == 0) ? xv0 : ((d == 1) ? xv1 : xv2);
            float arg = v * (PI_F * (float)(1 << l));
            float s, c;
            __sincosf(arg, &s, &c);
            sActs[i * PTS + pl] = (r < 3) ? s : c;
        }

        // ---- trilinear grid sample: rows 36..51, this thread does 4 channels
        {
            float fx = (xv0 + 1.f) * 31.5f;
            float fy = (xv1 + 1.f) * 31.5f;
            float fz = (xv2 + 1.f) * 31.5f;
            int ix0 = min(max((int)floorf(fx), 0), 63); int ix1 = min(ix0 + 1, 63);
            int iy0 = min(max((int)floorf(fy), 0), 63); int iy1 = min(iy0 + 1, 63);
            int iz0 = min(max((int)floorf(fz), 0), 63); int iz1 = min(iz0 + 1, 63);
            float wx1 = fx - (float)ix0, wx0 = 1.f - wx1;
            float wy1 = fy - (float)iy0, wy0 = 1.f - wy1;
            float wz1 = fz - (float)iz0, wz0 = 1.f - wz1;
            int   xs[2] = {ix0, ix1}, ys[2] = {iy0, iy1}, zs[2] = {iz0, iz1};
            float wxs[2] = {wx0, wx1}, wys[2] = {wy0, wy1}, wzs[2] = {wz0, wz1};
            float4 f4 = make_float4(0.f, 0.f, 0.f, 0.f);
#pragma unroll
            for (int iz = 0; iz < 2; iz++)
#pragma unroll
                for (int iy = 0; iy < 2; iy++)
#pragma unroll
                    for (int ix = 0; ix < 2; ix++) {
                        float w = wzs[iz] * wys[iy] * wxs[ix];
                        int vox = (zs[iz] * 64 + ys[iy]) * 64 + xs[ix];
                        float4 t = tg4[vox * 4 + sub];
                        f4.x = fmaf(w, t.x, f4.x);
                        f4.y = fmaf(w, t.y, f4.y);
                        f4.z = fmaf(w, t.z, f4.z);
                        f4.w = fmaf(w, t.w, f4.w);
                    }
            int fr = 36 + sub * 4;
            sActs[(fr + 0) * PTS + pl] = f4.x;
            sActs[(fr + 1) * PTS + pl] = f4.y;
            sActs[(fr + 2) * PTS + pl] = f4.z;
            sActs[(fr + 3) * PTS + pl] = f4.w;
        }
        __syncthreads();

        // ---- MLP: 52->128, then 3x 128->128 (all snake-activated)
        do_layer(g_W0T,              sB,       sActs, DIN,   tx, ty);
        do_layer(sWh,                sB + 128, sActs, NODES, tx, ty);
        do_layer(sWh + NODES*NODES,  sB + 256, sActs, NODES, tx, ty);
        do_layer(sWh + 2*NODES*NODES,sB + 384, sActs, NODES, tx, ty);

        // ---- output layer: 128 -> 1 (4 threads per point, shuffle reduce)
        {
            float r = 0.f;
            int kbase = sub * 32;
#pragma unroll 8
            for (int k = 0; k < 32; k++)
                r = fmaf(sWo[kbase + k], sActs[(kbase + k) * PTS + pl], r);
            r += __shfl_xor_sync(0xffffffffu, r, 1);
            r += __shfl_xor_sync(0xffffffffu, r, 2);
            if (sub == 0 && pg < Np) out[pg] = r + bo;
        }
        __syncthreads();   // protect sActs reads vs next tile's stage-1 writes
    }
}

// ---------------- launch ----------------
extern "C" void kernel_launch(void* const* d_in, const int* in_sizes, int n_in,
                              void* d_out, int out_size) {
    const float* x    = (const float*)d_in[0];
    const float* grid = (const float*)d_in[1];
    const float* W0   = (const float*)d_in[2];
    const float* b0   = (const float*)d_in[3];
    const float* Wh   = (const float*)d_in[4];
    const float* bh   = (const float*)d_in[5];
    const float* Wout = (const float*)d_in[6];
    const float* bout = (const float*)d_in[7];
    float* out = (float*)d_out;

    int Np = in_sizes[0] / 3;
    int ntiles = (Np + PTS - 1) / PTS;

    prep_grid_k<<<(NVOX + 255) / 256, 256>>>(grid);
    prep_w_k<<<64, 256>>>(W0, Wh);

    const int smem_bytes = (3 * NODES * NODES + NODES * PTS + 512 + 128) * (int)sizeof(float);
    cudaFuncSetAttribute(fvsrn_main, cudaFuncAttributeMaxDynamicSharedMemorySize, smem_bytes);
    fvsrn_main<<<148, THREADS, smem_bytes>>>(x, b0, bh, Wout, bout, out, Np, ntiles);
}